// round 1
// baseline (speedup 1.0000x reference)
#include <cuda_runtime.h>
#include <math_constants.h>

#define FULLMASK 0xffffffffu

// ---------------- problem constants ----------------
// D = 64, DY = 64, K = 32, TAU = 1
// ---------------- pipeline constants ---------------
constexpr int WPB  = 8;            // warps per block (256 threads)
constexpr int B1   = 1184;         // pass-1 blocks (8 * 148 SMs)
constexpr int NWRP = B1 * WPB;     // 9472 global warps
constexpr int C1   = B1 * 32;      // 37888 candidates after pass 1
constexpr int B2   = 37;           // 37 * 1024 == 37888
constexpr int C2   = B2 * 32;      // 1184 candidates after pass 2

// ---------------- scratch (no allocations allowed) ----------------
__device__ float g_cd1[C1];
__device__ int   g_ci1[C1];
__device__ float g_cd2[C2];
__device__ int   g_ci2[C2];
__device__ float g_bsum[B1];

// ---------------- helpers ----------------
// Select the 32 smallest entries of (sd[0..n), si[0..n)) using warp 0.
// Marks selected slots with +inf. Deterministic (value, then index tiebreak).
__device__ __forceinline__ void warp_select_32(volatile float* sd, const int* si, int n,
                                               float* gD, int* gI) {
    int lane = threadIdx.x & 31;
    for (int k = 0; k < 32; k++) {
        float mv = CUDART_INF_F;
        int   mi = 0;
        for (int j = lane; j < n; j += 32) {
            float v = sd[j];
            if (v < mv) { mv = v; mi = j; }
        }
#pragma unroll
        for (int o = 16; o; o >>= 1) {
            float ov = __shfl_xor_sync(FULLMASK, mv, o);
            int   oi = __shfl_xor_sync(FULLMASK, mi, o);
            if (ov < mv || (ov == mv && oi < mi)) { mv = ov; mi = oi; }
        }
        if (lane == 0) {
            gD[k] = mv;
            gI[k] = si[mi];
            sd[mi] = CUDART_INF_F;
        }
        __syncwarp();
    }
}

// ---------------- pass 1: distances + expsum + per-block top-32 ----------------
__global__ void __launch_bounds__(256) knn_pass1(const float* __restrict__ X,
                                                 const float* __restrict__ q,
                                                 int N) {
    const int tid  = threadIdx.x;
    const int lane = tid & 31;
    const int wid  = tid >> 5;
    const int gw   = blockIdx.x * WPB + wid;   // global warp id

    // query slice for this lane (2 floats of the 64-dim query)
    const float2 qv = *reinterpret_cast<const float2*>(q + 2 * lane);

    const float2* __restrict__ Xp = reinterpret_cast<const float2*>(X);

    float bestD = CUDART_INF_F;   // one top-32 slot per lane
    int   bestI = 0;
    float worst = CUDART_INF_F;   // cached max of the 32 slots (warp-uniform)
    float accE  = 0.f;            // sum of exp(-d) for this warp's rows (same in all lanes)

    for (int r = gw; r < N; r += 4 * NWRP) {
        float2 xv[4];
#pragma unroll
        for (int u = 0; u < 4; u++) {
            int rr = r + u * NWRP;
            if (rr < N) {
                xv[u] = Xp[(size_t)rr * 32 + lane];
            } else {
                xv[u] = make_float2(CUDART_INF_F, 0.f);  // -> d = inf -> exp = 0, never inserted
            }
        }
#pragma unroll
        for (int u = 0; u < 4; u++) {
            int rr = r + u * NWRP;
            float d0 = xv[u].x - qv.x;
            float d1 = xv[u].y - qv.y;
            float s  = fmaf(d0, d0, d1 * d1);
#pragma unroll
            for (int o = 16; o; o >>= 1) s += __shfl_xor_sync(FULLMASK, s, o);
            float d = sqrtf(s);
            accE += __expf(-d);             // TAU = 1
            if (d < worst) {
                // find the current worst slot and replace it
                float wm = bestD;
#pragma unroll
                for (int o = 16; o; o >>= 1) wm = fmaxf(wm, __shfl_xor_sync(FULLMASK, wm, o));
                unsigned m = __ballot_sync(FULLMASK, bestD == wm);
                int leader = __ffs(m) - 1;
                if (lane == leader) { bestD = d; bestI = rr; }
                float w2 = bestD;
#pragma unroll
                for (int o = 16; o; o >>= 1) w2 = fmaxf(w2, __shfl_xor_sync(FULLMASK, w2, o));
                worst = w2;
            }
        }
    }

    __shared__ float sd[256];
    __shared__ int   si[256];
    __shared__ float se[WPB];
    sd[tid] = bestD;
    si[tid] = bestI;
    if (lane == 0) se[wid] = accE;
    __syncthreads();

    if (wid == 0) {
        warp_select_32(sd, si, 256, g_cd1 + blockIdx.x * 32, g_ci1 + blockIdx.x * 32);
        if (lane == 0) {
            float s = 0.f;
#pragma unroll
            for (int i = 0; i < WPB; i++) s += se[i];
            g_bsum[blockIdx.x] = s;
        }
    }
}

// ---------------- pass 2: 37888 -> 1184 candidates ----------------
__global__ void __launch_bounds__(256) knn_pass2() {
    __shared__ float sd[1024];
    __shared__ int   si[1024];
    const int tid  = threadIdx.x;
    const int base = blockIdx.x * 1024;
    for (int j = tid; j < 1024; j += 256) {
        sd[j] = g_cd1[base + j];
        si[j] = g_ci1[base + j];
    }
    __syncthreads();
    if (tid < 32)
        warp_select_32(sd, si, 1024, g_cd2 + blockIdx.x * 32, g_ci2 + blockIdx.x * 32);
}

// ---------------- pass 3: final top-32 + normalizer + output ----------------
__global__ void __launch_bounds__(256) knn_pass3(const float* __restrict__ Y,
                                                 float* __restrict__ out) {
    __shared__ float sd[C2];
    __shared__ int   si[C2];
    __shared__ float selD[32];
    __shared__ int   selI[32];
    __shared__ float sred[256];
    const int tid = threadIdx.x;

    for (int j = tid; j < C2; j += 256) {
        sd[j] = g_cd2[j];
        si[j] = g_ci2[j];
    }

    // deterministic tree-sum of per-block exp sums
    float ps = 0.f;
    for (int j = tid; j < B1; j += 256) ps += g_bsum[j];
    sred[tid] = ps;
    __syncthreads();
#pragma unroll
    for (int o = 128; o; o >>= 1) {
        if (tid < o) sred[tid] += sred[tid + o];
        __syncthreads();
    }
    const float S = sred[0];

    if (tid < 32)
        warp_select_32(sd, si, C2, selD, selI);
    __syncthreads();

    if (tid < 64) {
        float acc = 0.f;
#pragma unroll
        for (int k = 0; k < 32; k++) {
            acc += __expf(-selD[k]) * __ldg(Y + (size_t)selI[k] * 64 + tid);
        }
        out[tid] = acc / S;
    }
}

// ---------------- launch ----------------
extern "C" void kernel_launch(void* const* d_in, const int* in_sizes, int n_in,
                              void* d_out, int out_size) {
    const float* X = (const float*)d_in[0];   // X_train [N, 64]
    const float* Y = (const float*)d_in[1];   // y_train [N, 64]
    const float* q = (const float*)d_in[2];   // X_missing [64]
    int N = in_sizes[0] / 64;

    knn_pass1<<<B1, 256>>>(X, q, N);
    knn_pass2<<<B2, 256>>>();
    knn_pass3<<<1, 256>>>(Y, (float*)d_out);
}

// round 2
// speedup vs baseline: 1.3000x; 1.3000x over previous
#include <cuda_runtime.h>
#include <math_constants.h>

#define FULLMASK 0xffffffffu

// ---------------- problem constants: D=64, DY=64, K=32, TAU=1 ----------------
constexpr int TPB  = 256;
constexpr int WPB  = 8;
constexpr int B1   = 592;                 // 4 blocks/SM on 148 SMs, one wave
constexpr int TOTW = B1 * WPB;            // 4736 warps
constexpr int RPI  = 8;                   // rows per warp per iter (2x4)
constexpr int SWEEP = TOTW * RPI;         // 37888 rows per sweep
constexpr int C1   = B1 * 32;             // 18944 candidates after pass 1
constexpr int B2   = 19;                  // ceil(18944/1024)
constexpr int C2   = B2 * 32;             // 608

// ---------------- scratch ----------------
__device__ float g_cd1[C1];
__device__ int   g_ci1[C1];
__device__ float g_cd2[C2];
__device__ int   g_ci2[C2];
__device__ float g_bsum[B1];

// Select the 32 smallest of (sd[0..n), si[0..n)); executed by ONE warp.
// Marks selected slots +inf. Deterministic (value, then index tiebreak).
__device__ __forceinline__ void warp_select_32(volatile float* sd, const int* si, int n,
                                               float* gD, int* gI) {
    int lane = threadIdx.x & 31;
    for (int k = 0; k < 32; k++) {
        float mv = CUDART_INF_F;
        int   mi = 0;
        for (int j = lane; j < n; j += 32) {
            float v = sd[j];
            if (v < mv) { mv = v; mi = j; }
        }
#pragma unroll
        for (int o = 16; o; o >>= 1) {
            float ov = __shfl_xor_sync(FULLMASK, mv, o);
            int   oi = __shfl_xor_sync(FULLMASK, mi, o);
            if (ov < mv || (ov == mv && oi < mi)) { mv = ov; mi = oi; }
        }
        if (lane == 0) {
            gD[k] = mv;
            gI[k] = si[mi];
            sd[mi] = CUDART_INF_F;
        }
        __syncwarp();
    }
}

__device__ __forceinline__ float dsq8(float4 a, float4 b, float4 qa, float4 qb) {
    float t, s0 = 0.f, s1 = 0.f;
    t = a.x - qa.x; s0 = fmaf(t, t, s0);
    t = a.y - qa.y; s1 = fmaf(t, t, s1);
    t = a.z - qa.z; s0 = fmaf(t, t, s0);
    t = a.w - qa.w; s1 = fmaf(t, t, s1);
    t = b.x - qb.x; s0 = fmaf(t, t, s0);
    t = b.y - qb.y; s1 = fmaf(t, t, s1);
    t = b.z - qb.z; s0 = fmaf(t, t, s0);
    t = b.w - qb.w; s1 = fmaf(t, t, s1);
    return s0 + s1;
}

// ---------------- pass 1 ----------------
__global__ void __launch_bounds__(256) knn_pass1(const float4* __restrict__ X4,
                                                 const float* __restrict__ q,
                                                 int N) {
    const int tid  = threadIdx.x;
    const int lane = tid & 31;
    const int wid  = tid >> 5;
    const int j    = lane & 7;     // position within 8-lane group
    const int sub  = lane >> 3;    // group id (0..3) = row offset
    const int gw   = blockIdx.x * WPB + wid;

    const float4 qa = *reinterpret_cast<const float4*>(q + 4 * j);
    const float4 qb = *reinterpret_cast<const float4*>(q + 32 + 4 * j);
    const float4 z4 = make_float4(0.f, 0.f, 0.f, 0.f);

    float b0 = CUDART_INF_F, b1 = CUDART_INF_F;  // per-lane top-2
    int   i0 = 0, i1 = 0;
    float acc = 0.f;

    int it = 0;
    for (int rb = gw * RPI; rb < N; rb += SWEEP, ++it) {
        const int r0 = rb + sub;
        const int r1 = rb + 4 + sub;
        const bool ok0 = r0 < N;
        const bool ok1 = r1 < N;
        const float4* p0 = X4 + (size_t)r0 * 16;
        const float4* p1 = X4 + (size_t)r1 * 16;
        float4 x0a = ok0 ? __ldg(p0 + j)     : z4;
        float4 x0b = ok0 ? __ldg(p0 + 8 + j) : z4;
        float4 x1a = ok1 ? __ldg(p1 + j)     : z4;
        float4 x1b = ok1 ? __ldg(p1 + 8 + j) : z4;

        float s0 = dsq8(x0a, x0b, qa, qb);
        float s1 = dsq8(x1a, x1b, qa, qb);
#pragma unroll
        for (int o = 1; o < 8; o <<= 1) {
            s0 += __shfl_xor_sync(FULLMASK, s0, o);
            s1 += __shfl_xor_sync(FULLMASK, s1, o);
        }
        float d0 = s0 * rsqrtf(fmaxf(s0, 1e-30f));
        float d1 = s1 * rsqrtf(fmaxf(s1, 1e-30f));
        acc += ok0 ? __expf(-d0) : 0.f;
        acc += ok1 ? __expf(-d1) : 0.f;

        // rotate topk responsibility across the 8 group lanes
        const int p0h = (2 * it)     & 7;
        const int p1h = (2 * it + 1) & 7;
        if (ok0 && p0h == j && d0 < b1) {
            if (d0 < b0) { b1 = b0; i1 = i0; b0 = d0; i0 = r0; }
            else         { b1 = d0; i1 = r0; }
        }
        if (ok1 && p1h == j && d1 < b1) {
            if (d1 < b0) { b1 = b0; i1 = i0; b0 = d1; i0 = r1; }
            else         { b1 = d1; i1 = r1; }
        }
    }

    __shared__ float sd[512];
    __shared__ int   si[512];
    __shared__ float se[WPB];
    sd[tid] = b0;        si[tid] = i0;
    sd[tid + 256] = b1;  si[tid + 256] = i1;
#pragma unroll
    for (int o = 16; o; o >>= 1) acc += __shfl_xor_sync(FULLMASK, acc, o);
    if (lane == 0) se[wid] = acc;
    __syncthreads();

    if (wid == 0) {
        warp_select_32(sd, si, 512, g_cd1 + blockIdx.x * 32, g_ci1 + blockIdx.x * 32);
        if (lane == 0) {
            float s = 0.f;
#pragma unroll
            for (int i = 0; i < WPB; i++) s += se[i];
            g_bsum[blockIdx.x] = s * 0.125f;   // each row counted by its 8 group lanes
        }
    }
}

// ---------------- pass 2: 18944 -> 608 ----------------
__global__ void __launch_bounds__(256) knn_pass2() {
    __shared__ float sd[1024];
    __shared__ int   si[1024];
    __shared__ float wd[256];
    __shared__ int   wi[256];
    const int tid  = threadIdx.x;
    const int lane = tid & 31;
    const int wid  = tid >> 5;
    const int base = blockIdx.x * 1024;
    const int n    = min(1024, C1 - base);

    for (int k = tid; k < 1024; k += 256) {
        sd[k] = (k < n) ? g_cd1[base + k] : CUDART_INF_F;
        si[k] = (k < n) ? g_ci1[base + k] : 0;
    }
    __syncthreads();
    // each warp selects top-32 of its 128-slice, in parallel
    warp_select_32(sd + wid * 128, si + wid * 128, 128, wd + wid * 32, wi + wid * 32);
    __syncthreads();
    if (wid == 0)
        warp_select_32(wd, wi, 256, g_cd2 + blockIdx.x * 32, g_ci2 + blockIdx.x * 32);
}

// ---------------- pass 3: 608 -> 32, normalize, output ----------------
__global__ void __launch_bounds__(256) knn_pass3(const float* __restrict__ Y,
                                                 float* __restrict__ out) {
    __shared__ float sd[C2];
    __shared__ int   si[C2];
    __shared__ float wd[256];
    __shared__ int   wi[256];
    __shared__ float selD[32];
    __shared__ int   selI[32];
    __shared__ float sred[256];
    const int tid = threadIdx.x;
    const int wid = tid >> 5;

    for (int k = tid; k < C2; k += 256) {
        sd[k] = g_cd2[k];
        si[k] = g_ci2[k];
    }
    // deterministic tree-sum of per-block exp sums
    float ps = 0.f;
    for (int k = tid; k < B1; k += 256) ps += g_bsum[k];
    sred[tid] = ps;
    __syncthreads();
#pragma unroll
    for (int o = 128; o; o >>= 1) {
        if (tid < o) sred[tid] += sred[tid + o];
        __syncthreads();
    }
    const float S = sred[0];

    // 8 warps on 76-element slices (8*76 = 608), then merge
    warp_select_32(sd + wid * 76, si + wid * 76, 76, wd + wid * 32, wi + wid * 32);
    __syncthreads();
    if (wid == 0)
        warp_select_32(wd, wi, 256, selD, selI);
    __syncthreads();

    if (tid < 64) {
        float accv = 0.f;
#pragma unroll
        for (int k = 0; k < 32; k++)
            accv += __expf(-selD[k]) * __ldg(Y + (size_t)selI[k] * 64 + tid);
        out[tid] = accv / S;
    }
}

// ---------------- launch ----------------
extern "C" void kernel_launch(void* const* d_in, const int* in_sizes, int n_in,
                              void* d_out, int out_size) {
    const float* X = (const float*)d_in[0];   // X_train [N, 64]
    const float* Y = (const float*)d_in[1];   // y_train [N, 64]
    const float* q = (const float*)d_in[2];   // X_missing [64]
    int N = in_sizes[0] / 64;

    knn_pass1<<<B1, TPB>>>((const float4*)X, q, N);
    knn_pass2<<<B2, TPB>>>();
    knn_pass3<<<1, TPB>>>(Y, (float*)d_out);
}